// round 7
// baseline (speedup 1.0000x reference)
#include <cuda_runtime.h>
#include <cstdint>

#define NB 8
#define RES 160
#define GCELLS (NB * RES * RES * RES)   // 32,768,000
#define EMA 0.95f
#define THRE 0.01f

// Scratch: per-cell max of (float bits of val) + 1. 0 == untouched sentinel.
// Zero-initialized at module load; sweep kernel resets touched entries so the
// state is identical at the start of every graph replay.
__device__ unsigned int g_scratch[GCELLS];

__device__ __forceinline__ int cell_coord(float p) {
    int g = (int)((p * 0.5f + 0.5f) * (float)RES);
    return min(max(g, 0), RES - 1);
}

__device__ __forceinline__ int lin_idx(int b, float x, float y, float z) {
    return ((b * RES + cell_coord(x)) * RES + cell_coord(y)) * RES + cell_coord(z);
}

// 8 points per thread: 6x float4 pts + 2x int4 bidx + 2x float4 val, all
// coalesced streaming loads (evict-first), then 8 fire-and-forget RED.MAX.
__global__ void scatter_max8_kernel(const float4* __restrict__ pts4,
                                    const int4* __restrict__ bidx4,
                                    const float4* __restrict__ val4,
                                    int n8) {
    int i = blockIdx.x * blockDim.x + threadIdx.x;
    if (i >= n8) return;

    float4 p0 = __ldcs(&pts4[6 * i + 0]);
    float4 p1 = __ldcs(&pts4[6 * i + 1]);
    float4 p2 = __ldcs(&pts4[6 * i + 2]);
    float4 p3 = __ldcs(&pts4[6 * i + 3]);
    float4 p4 = __ldcs(&pts4[6 * i + 4]);
    float4 p5 = __ldcs(&pts4[6 * i + 5]);
    int4   b0 = __ldcs(&bidx4[2 * i + 0]);
    int4   b1 = __ldcs(&bidx4[2 * i + 1]);
    float4 v0 = __ldcs(&val4[2 * i + 0]);
    float4 v1 = __ldcs(&val4[2 * i + 1]);

    // 24 floats = 8 points:
    int l0 = lin_idx(b0.x, p0.x, p0.y, p0.z);
    int l1 = lin_idx(b0.y, p0.w, p1.x, p1.y);
    int l2 = lin_idx(b0.z, p1.z, p1.w, p2.x);
    int l3 = lin_idx(b0.w, p2.y, p2.z, p2.w);
    int l4 = lin_idx(b1.x, p3.x, p3.y, p3.z);
    int l5 = lin_idx(b1.y, p3.w, p4.x, p4.y);
    int l6 = lin_idx(b1.z, p4.z, p4.w, p5.x);
    int l7 = lin_idx(b1.w, p5.y, p5.z, p5.w);

    // nonnegative floats: bit order == value order; +1 reserves 0 as sentinel.
    atomicMax(&g_scratch[l0], __float_as_uint(v0.x) + 1u);
    atomicMax(&g_scratch[l1], __float_as_uint(v0.y) + 1u);
    atomicMax(&g_scratch[l2], __float_as_uint(v0.z) + 1u);
    atomicMax(&g_scratch[l3], __float_as_uint(v0.w) + 1u);
    atomicMax(&g_scratch[l4], __float_as_uint(v1.x) + 1u);
    atomicMax(&g_scratch[l5], __float_as_uint(v1.y) + 1u);
    atomicMax(&g_scratch[l6], __float_as_uint(v1.z) + 1u);
    atomicMax(&g_scratch[l7], __float_as_uint(v1.w) + 1u);
}

// scalar tail (n % 8 != 0; unused for n = 4194304)
__global__ void scatter_max_tail_kernel(const float* __restrict__ pts,
                                        const int* __restrict__ bidx,
                                        const float* __restrict__ val,
                                        int start, int n) {
    int i = start + blockIdx.x * blockDim.x + threadIdx.x;
    if (i >= n) return;
    int lin = lin_idx(bidx[i], pts[3 * i + 0], pts[3 * i + 1], pts[3 * i + 2]);
    atomicMax(&g_scratch[lin], __float_as_uint(val[i]) + 1u);
}

__device__ __forceinline__ void sweep_vec(const float4* __restrict__ in,
                                          float4* __restrict__ out_grid,
                                          float4* __restrict__ out_occ,
                                          int i, int write_occ) {
    float4 g = __ldcs(&in[i]);
    uint4 s = reinterpret_cast<const uint4*>(g_scratch)[i];

    float4 o;
    o.x = s.x ? fmaxf(g.x * EMA, __uint_as_float(s.x - 1u)) : g.x;
    o.y = s.y ? fmaxf(g.y * EMA, __uint_as_float(s.y - 1u)) : g.y;
    o.z = s.z ? fmaxf(g.z * EMA, __uint_as_float(s.z - 1u)) : g.z;
    o.w = s.w ? fmaxf(g.w * EMA, __uint_as_float(s.w - 1u)) : g.w;

    __stcs(&out_grid[i], o);

    if (write_occ) {
        float4 q;
        q.x = (o.x > THRE) ? 1.0f : 0.0f;
        q.y = (o.y > THRE) ? 1.0f : 0.0f;
        q.z = (o.z > THRE) ? 1.0f : 0.0f;
        q.w = (o.w > THRE) ? 1.0f : 0.0f;
        __stcs(&out_occ[i], q);
    }

    // Reset only touched vectors so the next replay starts from zeros.
    if (s.x | s.y | s.z | s.w) {
        reinterpret_cast<uint4*>(g_scratch)[i] = make_uint4(0u, 0u, 0u, 0u);
    }
}

// 2 float4 per thread: thread handles vecs 2t and 2t+1 (32B contiguous).
__global__ void sweep2_kernel(const float4* __restrict__ in,
                              float4* __restrict__ out_grid,
                              float4* __restrict__ out_occ,
                              int nvec, int write_occ) {
    int t = blockIdx.x * blockDim.x + threadIdx.x;
    int i = 2 * t;
    if (i >= nvec) return;
    sweep_vec(in, out_grid, out_occ, i, write_occ);
    if (i + 1 < nvec) sweep_vec(in, out_grid, out_occ, i + 1, write_occ);
}

extern "C" void kernel_launch(void* const* d_in, const int* in_sizes, int n_in,
                              void* d_out, int out_size) {
    const float* grid_in = (const float*)d_in[0];   // occ_val_grid [8,160,160,160] f32
    const float* pts     = (const float*)d_in[1];   // [N,3] f32
    const int*   bidx    = (const int*)d_in[2];     // [N] i32
    const float* val     = (const float*)d_in[3];   // [N] f32

    int n = in_sizes[3];                 // N points
    float* out = (float*)d_out;

    int write_occ = (out_size >= 2 * GCELLS) ? 1 : 0;
    float4* out_grid = (float4*)out;
    float4* out_occ  = (float4*)(out + GCELLS);

    int n8 = n / 8;
    int rem = n - n8 * 8;
    if (n8 > 0) {
        int threads = 256;
        int blocks = (n8 + threads - 1) / threads;
        scatter_max8_kernel<<<blocks, threads>>>((const float4*)pts,
                                                 (const int4*)bidx,
                                                 (const float4*)val, n8);
    }
    if (rem > 0) {
        scatter_max_tail_kernel<<<1, 128>>>(pts, bidx, val, n8 * 8, n);
    }
    {
        int nvec = GCELLS / 4;           // 8,192,000
        int threads = 256;
        int nthreads_total = (nvec + 1) / 2;
        int blocks = (nthreads_total + threads - 1) / threads;
        sweep2_kernel<<<blocks, threads>>>((const float4*)grid_in, out_grid,
                                           out_occ, nvec, write_occ);
    }
}

// round 11
// speedup vs baseline: 1.2813x; 1.2813x over previous
#include <cuda_runtime.h>
#include <cstdint>

#define NB 8
#define RES 160
#define GCELLS (NB * RES * RES * RES)   // 32,768,000
#define EMA 0.95f
#define THRE 0.01f

// Scratch: per-cell max of (float bits of val) + 1. 0 == untouched sentinel.
// Zero-initialized at module load; sweep kernel resets touched entries so the
// state is identical at the start of every graph replay.
__device__ unsigned int g_scratch[GCELLS];

__device__ __forceinline__ int cell_coord(float p) {
    int g = (int)((p * 0.5f + 0.5f) * (float)RES);
    return min(max(g, 0), RES - 1);
}

__device__ __forceinline__ int lin_idx(int b, float x, float y, float z) {
    return ((b * RES + cell_coord(x)) * RES + cell_coord(y)) * RES + cell_coord(z);
}

// 4 points per thread, batch-partitioned: only applies points whose bidx is in
// [b_lo, b_hi). Launched twice so each pass's atomic working set (65.5 MB)
// stays resident in the 126 MB L2 instead of thrashing.
__global__ void scatter_max4_part_kernel(const float4* __restrict__ pts4,
                                         const int4* __restrict__ bidx4,
                                         const float4* __restrict__ val4,
                                         int n4, int b_lo, int b_hi) {
    int i = blockIdx.x * blockDim.x + threadIdx.x;
    if (i >= n4) return;

    float4 p0 = __ldcs(&pts4[3 * i + 0]);
    float4 p1 = __ldcs(&pts4[3 * i + 1]);
    float4 p2 = __ldcs(&pts4[3 * i + 2]);
    int4   b  = __ldcs(&bidx4[i]);
    float4 v  = __ldcs(&val4[i]);

    // pt0=(p0.x,p0.y,p0.z) pt1=(p0.w,p1.x,p1.y) pt2=(p1.z,p1.w,p2.x) pt3=(p2.y,p2.z,p2.w)
    if (b.x >= b_lo && b.x < b_hi) {
        int l = lin_idx(b.x, p0.x, p0.y, p0.z);
        atomicMax(&g_scratch[l], __float_as_uint(v.x) + 1u);
    }
    if (b.y >= b_lo && b.y < b_hi) {
        int l = lin_idx(b.y, p0.w, p1.x, p1.y);
        atomicMax(&g_scratch[l], __float_as_uint(v.y) + 1u);
    }
    if (b.z >= b_lo && b.z < b_hi) {
        int l = lin_idx(b.z, p1.z, p1.w, p2.x);
        atomicMax(&g_scratch[l], __float_as_uint(v.z) + 1u);
    }
    if (b.w >= b_lo && b.w < b_hi) {
        int l = lin_idx(b.w, p2.y, p2.z, p2.w);
        atomicMax(&g_scratch[l], __float_as_uint(v.w) + 1u);
    }
}

// scalar tail (n % 4 != 0; unused for n = 4194304)
__global__ void scatter_max_tail_kernel(const float* __restrict__ pts,
                                        const int* __restrict__ bidx,
                                        const float* __restrict__ val,
                                        int start, int n) {
    int i = start + blockIdx.x * blockDim.x + threadIdx.x;
    if (i >= n) return;
    int lin = lin_idx(bidx[i], pts[3 * i + 0], pts[3 * i + 1], pts[3 * i + 2]);
    atomicMax(&g_scratch[lin], __float_as_uint(val[i]) + 1u);
}

// 1 float4 per thread, fully coalesced (reverted from the 2-vec regression).
__global__ void sweep_kernel(const float4* __restrict__ in,
                             float4* __restrict__ out_grid,
                             float4* __restrict__ out_occ,
                             int nvec, int write_occ) {
    int i = blockIdx.x * blockDim.x + threadIdx.x;
    if (i >= nvec) return;

    float4 g = __ldcs(&in[i]);
    uint4 s = reinterpret_cast<const uint4*>(g_scratch)[i];

    float4 o;
    o.x = s.x ? fmaxf(g.x * EMA, __uint_as_float(s.x - 1u)) : g.x;
    o.y = s.y ? fmaxf(g.y * EMA, __uint_as_float(s.y - 1u)) : g.y;
    o.z = s.z ? fmaxf(g.z * EMA, __uint_as_float(s.z - 1u)) : g.z;
    o.w = s.w ? fmaxf(g.w * EMA, __uint_as_float(s.w - 1u)) : g.w;

    __stcs(&out_grid[i], o);

    if (write_occ) {
        float4 q;
        q.x = (o.x > THRE) ? 1.0f : 0.0f;
        q.y = (o.y > THRE) ? 1.0f : 0.0f;
        q.z = (o.z > THRE) ? 1.0f : 0.0f;
        q.w = (o.w > THRE) ? 1.0f : 0.0f;
        __stcs(&out_occ[i], q);
    }

    // Reset only touched vectors so the next replay starts from zeros.
    if (s.x | s.y | s.z | s.w) {
        reinterpret_cast<uint4*>(g_scratch)[i] = make_uint4(0u, 0u, 0u, 0u);
    }
}

extern "C" void kernel_launch(void* const* d_in, const int* in_sizes, int n_in,
                              void* d_out, int out_size) {
    const float* grid_in = (const float*)d_in[0];   // occ_val_grid [8,160,160,160] f32
    const float* pts     = (const float*)d_in[1];   // [N,3] f32
    const int*   bidx    = (const int*)d_in[2];     // [N] i32
    const float* val     = (const float*)d_in[3];   // [N] f32

    int n = in_sizes[3];                 // N points
    float* out = (float*)d_out;

    int write_occ = (out_size >= 2 * GCELLS) ? 1 : 0;
    float4* out_grid = (float4*)out;
    float4* out_occ  = (float4*)(out + GCELLS);

    int n4 = n / 4;
    int rem = n - n4 * 4;
    if (n4 > 0) {
        int threads = 256;
        int blocks = (n4 + threads - 1) / threads;
        // Pass 1: batches 0..3 (scratch halves stay L2-resident per pass)
        scatter_max4_part_kernel<<<blocks, threads>>>((const float4*)pts,
                                                      (const int4*)bidx,
                                                      (const float4*)val,
                                                      n4, 0, NB / 2);
        // Pass 2: batches 4..7
        scatter_max4_part_kernel<<<blocks, threads>>>((const float4*)pts,
                                                      (const int4*)bidx,
                                                      (const float4*)val,
                                                      n4, NB / 2, NB);
    }
    if (rem > 0) {
        scatter_max_tail_kernel<<<1, 128>>>(pts, bidx, val, n4 * 4, n);
    }
    {
        int nvec = GCELLS / 4;           // 8,192,000
        int threads = 256;
        int blocks = (nvec + threads - 1) / threads;
        sweep_kernel<<<blocks, threads>>>((const float4*)grid_in, out_grid,
                                          out_occ, nvec, write_occ);
    }
}